// round 8
// baseline (speedup 1.0000x reference)
#include <cuda_runtime.h>
#include <cstdint>
#include <cstddef>

// Problem constants
#define HID    512
#define NOBJC  151
#define NRELC  51
#define POOL   4096

// Shared-memory strides (in 32-bit words), padded for conflict-free MMA fragment loads
#define ASTR 36    // A tile: [128][36]   (bank = 4*(lane/4) + lane%4 -> conflict-free)
#define BSTR 136   // B tile: [32][136]   (bank = 8*(lane%4) + lane/4 -> conflict-free)
#define VSTR 132   // V tile: [128][132]
#define WSTR 72    // Wrel tile: [128][72]

#define K1_SMEM ((2*128*ASTR + 2*32*BSTR) * 4)
#define K2_SMEM ((2*128*ASTR + 2*32*BSTR + 128*VSTR + 128*WSTR + 3*128) * 4)

// Materialized edge_rep (8192 x 1024 fp32, 32 MB -> L2-resident for the gathers)
__device__ float g_edge_rep[(size_t)8192 * 1024];

__device__ __forceinline__ unsigned f2tf(float f) {
    unsigned u;
    asm("cvt.rna.tf32.f32 %0, %1;" : "=r"(u) : "f"(f));
    return u;
}

__device__ __forceinline__ void mma8(float (&d)[4], const unsigned (&a)[4], const unsigned (&b)[2]) {
    asm volatile(
        "mma.sync.aligned.m16n8k8.row.col.f32.tf32.tf32.f32 "
        "{%0,%1,%2,%3},{%4,%5,%6,%7},{%8,%9},{%0,%1,%2,%3};\n"
        : "+f"(d[0]), "+f"(d[1]), "+f"(d[2]), "+f"(d[3])
        : "r"(a[0]), "r"(a[1]), "r"(a[2]), "r"(a[3]), "r"(b[0]), "r"(b[1]));
}

// ---- staging: gmem(float4) -> regs, regs -> smem (cvt to tf32) -------------

__device__ __forceinline__ void stA(unsigned* __restrict__ Ab, const float4 (&ra)[4], int tid) {
#pragma unroll
    for (int i = 0; i < 4; i++) {
        int s = tid + i * 256, r = s >> 3, kq = s & 7;
        unsigned* p = Ab + r * ASTR + kq * 4;
        p[0] = f2tf(ra[i].x); p[1] = f2tf(ra[i].y); p[2] = f2tf(ra[i].z); p[3] = f2tf(ra[i].w);
    }
}
__device__ __forceinline__ void stB(unsigned* __restrict__ Bb, const float4 (&rb)[4], int tid) {
#pragma unroll
    for (int i = 0; i < 4; i++) {
        int s = tid + i * 256, kk = s >> 5, cq = s & 31;
        unsigned* p = Bb + kk * BSTR + cq * 4;
        p[0] = f2tf(rb[i].x); p[1] = f2tf(rb[i].y); p[2] = f2tf(rb[i].z); p[3] = f2tf(rb[i].w);
    }
}

// Gathered A load for K2: prod_rep[i,k] = edge_rep[k<512 ? p0 : p1][k]
__device__ __forceinline__ void ldA_g(float4 (&ra)[4], const float* __restrict__ er,
                                      const int* __restrict__ rows, int k0, int tid) {
#pragma unroll
    for (int i = 0; i < 4; i++) {
        int s = tid + i * 256, r = s >> 3, kq = s & 7;
        ra[i] = __ldg((const float4*)(er + (size_t)rows[r] * 1024 + k0 + kq * 4));
    }
}
__device__ __forceinline__ void ldB_main(float4 (&rb)[4], const float* __restrict__ Wpc,
                                         int n0, int k0, int tid) {
#pragma unroll
    for (int i = 0; i < 4; i++) {
        int s = tid + i * 256, kk = s >> 5, cq = s & 31;
        rb[i] = __ldg((const float4*)(Wpc + (size_t)(k0 + kk) * POOL + n0 + cq * 4));
    }
}
// Virtual tile 32: B = W_ctx (1024 x 51) zero-padded to 128 cols
__device__ __forceinline__ void ldB_ctx(float4 (&rb)[4], const float* __restrict__ Wctx,
                                        int k0, int tid) {
#pragma unroll
    for (int i = 0; i < 4; i++) {
        int s = tid + i * 256, kk = s >> 5, cq = s & 31, cb = cq * 4;
        const float* w = Wctx + (size_t)(k0 + kk) * NRELC;
        rb[i].x = (cb + 0 < NRELC) ? __ldg(w + cb + 0) : 0.f;
        rb[i].y = (cb + 1 < NRELC) ? __ldg(w + cb + 1) : 0.f;
        rb[i].z = (cb + 2 < NRELC) ? __ldg(w + cb + 2) : 0.f;
        rb[i].w = (cb + 3 < NRELC) ? __ldg(w + cb + 3) : 0.f;
    }
}

// One BK=32 compute step: 4 k-substeps of m16n8k8, warp tile 64x32 (2x4 warp grid)
__device__ __forceinline__ void mma_tile(float (&acc)[4][4][4], const unsigned* __restrict__ Ab,
                                         const unsigned* __restrict__ Bb, int wr, int wc, int lane) {
#pragma unroll
    for (int ks = 0; ks < 4; ks++) {
        unsigned af[4][4], bf[4][2];
#pragma unroll
        for (int tm = 0; tm < 4; tm++) {
            const unsigned* p = Ab + (wr * 64 + tm * 16 + (lane >> 2)) * ASTR + ks * 8 + (lane & 3);
            af[tm][0] = p[0];
            af[tm][1] = p[8 * ASTR];
            af[tm][2] = p[4];
            af[tm][3] = p[8 * ASTR + 4];
        }
#pragma unroll
        for (int tn = 0; tn < 4; tn++) {
            const unsigned* p = Bb + (ks * 8 + (lane & 3)) * BSTR + wc * 32 + tn * 8 + (lane >> 2);
            bf[tn][0] = p[0];
            bf[tn][1] = p[4 * BSTR];
        }
#pragma unroll
        for (int tm = 0; tm < 4; tm++)
#pragma unroll
            for (int tn = 0; tn < 4; tn++)
                mma8(acc[tm][tn], af[tm], bf[tn]);
    }
}

// ============================================================================
// Kernel 1: edge_rep = edge_ctx(8192x512) @ W_post_emb(512x1024) + b  (tf32 MMA)
// ============================================================================
__global__ void __launch_bounds__(256, 1) k1_edge_rep(
    const float* __restrict__ A, const float* __restrict__ B, const float* __restrict__ bias) {
    extern __shared__ unsigned sm1[];
    unsigned* As = sm1;
    unsigned* Bs = sm1 + 2 * 128 * ASTR;
    const int tid = threadIdx.x, lane = tid & 31, wid = tid >> 5;
    const int wr = wid >> 2, wc = wid & 3;
    const int m0 = blockIdx.x * 128, n0 = blockIdx.y * 128;

    float acc[4][4][4];
#pragma unroll
    for (int a = 0; a < 4; a++)
#pragma unroll
        for (int b = 0; b < 4; b++)
#pragma unroll
            for (int c = 0; c < 4; c++) acc[a][b][c] = 0.f;

    float4 ra[4], rb[4];
#pragma unroll
    for (int i = 0; i < 4; i++) {
        int s = tid + i * 256;
        { int r = s >> 3, kq = s & 7;
          ra[i] = __ldg((const float4*)(A + (size_t)(m0 + r) * HID + kq * 4)); }
        { int kk = s >> 5, cq = s & 31;
          rb[i] = __ldg((const float4*)(B + (size_t)kk * 1024 + n0 + cq * 4)); }
    }
    stA(As, ra, tid);
    stB(Bs, rb, tid);
    __syncthreads();

    int buf = 0;
    for (int kt = 0; kt < 16; kt++) {
        if (kt < 15) {
            int k0 = (kt + 1) * 32;
#pragma unroll
            for (int i = 0; i < 4; i++) {
                int s = tid + i * 256;
                { int r = s >> 3, kq = s & 7;
                  ra[i] = __ldg((const float4*)(A + (size_t)(m0 + r) * HID + k0 + kq * 4)); }
                { int kk = s >> 5, cq = s & 31;
                  rb[i] = __ldg((const float4*)(B + (size_t)(k0 + kk) * 1024 + n0 + cq * 4)); }
            }
        }
        mma_tile(acc, As + buf * 128 * ASTR, Bs + buf * 32 * BSTR, wr, wc, lane);
        if (kt < 15) {
            stA(As + (buf ^ 1) * 128 * ASTR, ra, tid);
            stB(Bs + (buf ^ 1) * 32 * BSTR, rb, tid);
        }
        __syncthreads();
        buf ^= 1;
    }

#pragma unroll
    for (int tm = 0; tm < 4; tm++) {
        int r = m0 + wr * 64 + tm * 16 + (lane >> 2);
#pragma unroll
        for (int tn = 0; tn < 4; tn++) {
            int c = n0 + wc * 32 + tn * 8 + 2 * (lane & 3);
            float2 bb = *(const float2*)(bias + c);
            float2 v0 = make_float2(acc[tm][tn][0] + bb.x, acc[tm][tn][1] + bb.y);
            float2 v1 = make_float2(acc[tm][tn][2] + bb.x, acc[tm][tn][3] + bb.y);
            *(float2*)(g_edge_rep + (size_t)r * 1024 + c) = v0;
            *(float2*)(g_edge_rep + (size_t)(r + 8) * 1024 + c) = v1;
        }
    }
}

// ============================================================================
// Kernel 2: fused  gather -> (prod@Wpc+b) * U -> @Wrel  (+ prod@Wctx via the
// 33rd "virtual" n-tile with identity contraction) -> + biases + freq lookup
// One CTA = 128 relation rows. Grid = 512.
// ============================================================================
__global__ void __launch_bounds__(256, 1) k2_main(
    const int* __restrict__ pair_idx, const int* __restrict__ obj_preds,
    const float* __restrict__ U,
    const float* __restrict__ Wpc, const float* __restrict__ bpc,
    const float* __restrict__ Wrel, const float* __restrict__ brel,
    const float* __restrict__ Wctx, const float* __restrict__ bctx,
    const float* __restrict__ freq, float* __restrict__ out) {
    extern __shared__ unsigned sm2[];
    unsigned* As = sm2;                      // [2][128][ASTR]
    unsigned* Bs = As + 2 * 128 * ASTR;      // [2][32][BSTR]
    unsigned* Vs = Bs + 2 * 32 * BSTR;       // [128][VSTR]
    unsigned* Ws = Vs + 128 * VSTR;          // [128][WSTR]
    int* rows0 = (int*)(Ws + 128 * WSTR);
    int* rows1 = rows0 + 128;
    int* pp    = rows1 + 128;

    const float* er = g_edge_rep;
    const int tid = threadIdx.x, lane = tid & 31, wid = tid >> 5;
    const int wr = wid >> 2, wc = wid & 3;
    const int m0 = blockIdx.x * 128;

    if (tid < 128) {
        int i = m0 + tid;
        int p0 = pair_idx[2 * i], p1 = pair_idx[2 * i + 1];
        rows0[tid] = p0;
        rows1[tid] = p1;
        pp[tid] = obj_preds[p0] * NOBJC + obj_preds[p1];
    }
    __syncthreads();

    // Persistent output accumulator: 128x64 tile, warp tile 64x16 (2x4 warp grid)
    float acc2[4][2][4];
#pragma unroll
    for (int a = 0; a < 4; a++)
#pragma unroll
        for (int b = 0; b < 2; b++)
#pragma unroll
            for (int c = 0; c < 4; c++) acc2[a][b][c] = 0.f;

    float4 ra[4], rb[4];

    for (int nt = 0; nt < 33; nt++) {
        const int n0 = nt * 128;

        float acc[4][4][4];
#pragma unroll
        for (int a = 0; a < 4; a++)
#pragma unroll
            for (int b = 0; b < 4; b++)
#pragma unroll
                for (int c = 0; c < 4; c++) acc[a][b][c] = 0.f;

        // ---- G = prod_rep_tile @ B_tile  (K = 1024, BK = 32, double-buffered) ----
        ldA_g(ra, er, rows0, 0, tid);
        if (nt < 32) ldB_main(rb, Wpc, n0, 0, tid);
        else         ldB_ctx(rb, Wctx, 0, tid);
        stA(As, ra, tid);
        stB(Bs, rb, tid);
        __syncthreads();

        int buf = 0;
        for (int kt = 0; kt < 32; kt++) {
            if (kt < 31) {
                int k0 = (kt + 1) * 32;
                ldA_g(ra, er, (k0 < HID) ? rows0 : rows1, k0, tid);
                if (nt < 32) ldB_main(rb, Wpc, n0, k0, tid);
                else         ldB_ctx(rb, Wctx, k0, tid);
            }
            mma_tile(acc, As + buf * 128 * ASTR, Bs + buf * 32 * BSTR, wr, wc, lane);
            if (kt < 31) {
                stA(As + (buf ^ 1) * 128 * ASTR, ra, tid);
                stB(Bs + (buf ^ 1) * 32 * BSTR, rb, tid);
            }
            __syncthreads();
            buf ^= 1;
        }

        // ---- V = (G + b_post_cat) * U  (or V = G for the virtual ctx tile) -> smem
        //      and load the Wrel chunk (or identity) ----
        if (nt < 32) {
#pragma unroll
            for (int tm = 0; tm < 4; tm++) {
                int rl = wr * 64 + tm * 16 + (lane >> 2);
                const float* u0p = U + (size_t)(m0 + rl) * POOL + n0;
                const float* u1p = U + (size_t)(m0 + rl + 8) * POOL + n0;
#pragma unroll
                for (int tn = 0; tn < 4; tn++) {
                    int cl = wc * 32 + tn * 8 + 2 * (lane & 3);
                    float2 bb = *(const float2*)(bpc + n0 + cl);
                    float2 u0 = __ldg((const float2*)(u0p + cl));
                    float2 u1 = __ldg((const float2*)(u1p + cl));
                    Vs[rl * VSTR + cl]           = f2tf((acc[tm][tn][0] + bb.x) * u0.x);
                    Vs[rl * VSTR + cl + 1]       = f2tf((acc[tm][tn][1] + bb.y) * u0.y);
                    Vs[(rl + 8) * VSTR + cl]     = f2tf((acc[tm][tn][2] + bb.x) * u1.x);
                    Vs[(rl + 8) * VSTR + cl + 1] = f2tf((acc[tm][tn][3] + bb.y) * u1.y);
                }
            }
#pragma unroll 4
            for (int i = 0; i < 32; i++) {
                int s = tid + i * 256, nn = s >> 6, c = s & 63;
                float v = (c < NRELC) ? __ldg(Wrel + (size_t)(n0 + nn) * NRELC + c) : 0.f;
                Ws[nn * WSTR + c] = f2tf(v);
            }
        } else {
#pragma unroll
            for (int tm = 0; tm < 4; tm++) {
                int rl = wr * 64 + tm * 16 + (lane >> 2);
#pragma unroll
                for (int tn = 0; tn < 4; tn++) {
                    int cl = wc * 32 + tn * 8 + 2 * (lane & 3);
                    Vs[rl * VSTR + cl]           = f2tf(acc[tm][tn][0]);
                    Vs[rl * VSTR + cl + 1]       = f2tf(acc[tm][tn][1]);
                    Vs[(rl + 8) * VSTR + cl]     = f2tf(acc[tm][tn][2]);
                    Vs[(rl + 8) * VSTR + cl + 1] = f2tf(acc[tm][tn][3]);
                }
            }
#pragma unroll 4
            for (int i = 0; i < 32; i++) {
                int s = tid + i * 256, nn = s >> 6, c = s & 63;
                Ws[nn * WSTR + c] = (nn == c && c < NRELC) ? 0x3F800000u : 0u;
            }
        }
        __syncthreads();

        // ---- acc2 += V(128x128) @ Ws(128x64) ----
#pragma unroll
        for (int kk = 0; kk < 16; kk++) {
            unsigned af[4][4], bf[2][2];
#pragma unroll
            for (int tm = 0; tm < 4; tm++) {
                const unsigned* p = Vs + (wr * 64 + tm * 16 + (lane >> 2)) * VSTR + kk * 8 + (lane & 3);
                af[tm][0] = p[0];
                af[tm][1] = p[8 * VSTR];
                af[tm][2] = p[4];
                af[tm][3] = p[8 * VSTR + 4];
            }
#pragma unroll
            for (int tn = 0; tn < 2; tn++) {
                const unsigned* p = Ws + (kk * 8 + (lane & 3)) * WSTR + wc * 16 + tn * 8 + (lane >> 2);
                bf[tn][0] = p[0];
                bf[tn][1] = p[4 * WSTR];
            }
#pragma unroll
            for (int tm = 0; tm < 4; tm++)
#pragma unroll
                for (int tn = 0; tn < 2; tn++)
                    mma8(acc2[tm][tn], af[tm], bf[tn]);
        }
        __syncthreads();
    }

    // ---- epilogue: + b_rel + b_ctx + freq_table[pair_pred] ----
#pragma unroll
    for (int tm = 0; tm < 4; tm++) {
        int rl = wr * 64 + tm * 16 + (lane >> 2);
#pragma unroll
        for (int tn = 0; tn < 2; tn++) {
            int c = wc * 16 + tn * 8 + 2 * (lane & 3);
#pragma unroll
            for (int q = 0; q < 4; q++) {
                int row = rl + ((q >= 2) ? 8 : 0);
                int col = c + (q & 1);
                if (col < NRELC) {
                    float v = acc2[tm][tn][q] + __ldg(brel + col) + __ldg(bctx + col)
                            + __ldg(freq + (size_t)pp[row] * NRELC + col);
                    out[(size_t)(m0 + row) * NRELC + col] = v;
                }
            }
        }
    }
}

// ============================================================================
// Launch
// ============================================================================
extern "C" void kernel_launch(void* const* d_in, const int* in_sizes, int n_in,
                              void* d_out, int out_size) {
    (void)in_sizes; (void)n_in; (void)out_size;
    const float* edge_ctx  = (const float*)d_in[0];
    const int*   obj_preds = (const int*)d_in[1];
    const int*   pair_idx  = (const int*)d_in[2];
    const float* U         = (const float*)d_in[3];
    const float* Wpe       = (const float*)d_in[4];
    const float* bpe       = (const float*)d_in[5];
    const float* Wpc       = (const float*)d_in[6];
    const float* bpc       = (const float*)d_in[7];
    const float* Wrel      = (const float*)d_in[8];
    const float* brel      = (const float*)d_in[9];
    const float* Wctx      = (const float*)d_in[10];
    const float* bctx      = (const float*)d_in[11];
    const float* freq      = (const float*)d_in[12];
    float* out = (float*)d_out;

    cudaFuncSetAttribute(k1_edge_rep, cudaFuncAttributeMaxDynamicSharedMemorySize, K1_SMEM);
    cudaFuncSetAttribute(k2_main,     cudaFuncAttributeMaxDynamicSharedMemorySize, K2_SMEM);

    k1_edge_rep<<<dim3(64, 8), 256, K1_SMEM>>>(edge_ctx, Wpe, bpe);
    k2_main<<<512, 256, K2_SMEM>>>(pair_idx, obj_preds, U, Wpc, bpc,
                                   Wrel, brel, Wctx, bctx, freq, out);
}

// round 10
// speedup vs baseline: 1.0891x; 1.0891x over previous
#include <cuda_runtime.h>
#include <cstdint>
#include <cstddef>

// Problem constants
#define HID    512
#define NOBJC  151
#define NRELC  51
#define POOL   4096

// ---------------- k1 (edge_rep) constants ----------------
#define ASTR 36
#define BSTR 136
#define K1_SMEM ((2*128*ASTR + 2*32*BSTR) * 4)

// ---------------- k2 constants ----------------
// Block tile: BM=128, BN=256, BK=16, 4 cp.async stages, 8 warps as 2x4 grid,
// warp tile 64x64 (acc[4][8][4]).
#define A2STR 20      // A stage tile [128 rows][16 k] padded to 20 words/row
#define B2STR 264     // B stage tile [16 k][256 n] padded to 264 words/row
#define VSTR  132
#define WSTR  72

#define ABUF (128*A2STR*4)   // 10240 B
#define BBUF (16*B2STR*4)    // 16896 B
#define OFFA 0
#define OFFB (OFFA + 4*ABUF)             // 40960
#define OFFV (OFFB + 4*BBUF)             // 108544
#define OFFW (OFFV + 128*VSTR*4)         // 176128
#define OFFI (OFFW + 128*WSTR*4)         // 212992
#define K2S  (OFFI + 3*128*4)            // 214528

// Prepared (pre-rounded tf32) weight copies + materialized edge_rep
__device__ float g_edge_rep[(size_t)8192 * 1024];   // tf32-rounded
__device__ float g_wpc[(size_t)1024 * 4096];        // tf32-rounded W_post_cat
__device__ float g_wctx[(size_t)1024 * 256];        // tf32-rounded W_ctx, zero-padded

// ---------------------------------------------------------------------------
__device__ __forceinline__ unsigned f2tf(float f) {
    unsigned u;
    asm("cvt.rna.tf32.f32 %0, %1;" : "=r"(u) : "f"(f));
    return u;
}
__device__ __forceinline__ uint32_t s2u(const void* p) {
    uint32_t a;
    asm("{ .reg .u64 t; cvta.to.shared.u64 t, %1; cvt.u32.u64 %0, t; }" : "=r"(a) : "l"(p));
    return a;
}
__device__ __forceinline__ void cp16(uint32_t dst, const void* src) {
    asm volatile("cp.async.cg.shared.global [%0], [%1], 16;" :: "r"(dst), "l"(src));
}
__device__ __forceinline__ void cp_commit() {
    asm volatile("cp.async.commit_group;" ::: "memory");
}
__device__ __forceinline__ void cp_wait2() {
    asm volatile("cp.async.wait_group 2;" ::: "memory");
}
__device__ __forceinline__ void mma8(float (&d)[4], const unsigned (&a)[4], const unsigned (&b)[2]) {
    asm volatile(
        "mma.sync.aligned.m16n8k8.row.col.f32.tf32.tf32.f32 "
        "{%0,%1,%2,%3},{%4,%5,%6,%7},{%8,%9},{%0,%1,%2,%3};\n"
        : "+f"(d[0]), "+f"(d[1]), "+f"(d[2]), "+f"(d[3])
        : "r"(a[0]), "r"(a[1]), "r"(a[2]), "r"(a[3]), "r"(b[0]), "r"(b[1]));
}

// ===========================================================================
// Kernel 0: pre-round weights to tf32 bit patterns (so k2 can raw-copy them)
// ===========================================================================
__global__ void k0_prep(const float* __restrict__ Wpc, const float* __restrict__ Wctx) {
    int bid = blockIdx.x, tid = threadIdx.x;
    if (bid < 4096) {
        // Wpc: 1024*4096 floats = 1,048,576 float4
        int idx = bid * 256 + tid;
        float4 v = __ldg((const float4*)Wpc + idx);
        float4 o;
        o.x = __uint_as_float(f2tf(v.x));
        o.y = __uint_as_float(f2tf(v.y));
        o.z = __uint_as_float(f2tf(v.z));
        o.w = __uint_as_float(f2tf(v.w));
        ((float4*)g_wpc)[idx] = o;
    } else {
        // Wctx padded: 1024 x 256
        int idx = (bid - 4096) * 256 + tid;   // < 262144
        int k = idx >> 8, c = idx & 255;
        float v = (c < NRELC) ? __uint_as_float(f2tf(__ldg(Wctx + (size_t)k * NRELC + c))) : 0.f;
        g_wctx[idx] = v;
    }
}

// ===========================================================================
// Kernel 1: edge_rep = tf32round(edge_ctx @ W_post_emb + b)   (legacy tf32 mma)
// ===========================================================================
__device__ __forceinline__ void stA1(unsigned* __restrict__ Ab, const float4 (&ra)[4], int tid) {
#pragma unroll
    for (int i = 0; i < 4; i++) {
        int s = tid + i * 256, r = s >> 3, kq = s & 7;
        unsigned* p = Ab + r * ASTR + kq * 4;
        p[0] = f2tf(ra[i].x); p[1] = f2tf(ra[i].y); p[2] = f2tf(ra[i].z); p[3] = f2tf(ra[i].w);
    }
}
__device__ __forceinline__ void stB1(unsigned* __restrict__ Bb, const float4 (&rb)[4], int tid) {
#pragma unroll
    for (int i = 0; i < 4; i++) {
        int s = tid + i * 256, kk = s >> 5, cq = s & 31;
        unsigned* p = Bb + kk * BSTR + cq * 4;
        p[0] = f2tf(rb[i].x); p[1] = f2tf(rb[i].y); p[2] = f2tf(rb[i].z); p[3] = f2tf(rb[i].w);
    }
}
__device__ __forceinline__ void mma_tile1(float (&acc)[4][4][4], const unsigned* __restrict__ Ab,
                                          const unsigned* __restrict__ Bb, int wr, int wc, int lane) {
#pragma unroll
    for (int ks = 0; ks < 4; ks++) {
        unsigned af[4][4], bf[4][2];
#pragma unroll
        for (int tm = 0; tm < 4; tm++) {
            const unsigned* p = Ab + (wr * 64 + tm * 16 + (lane >> 2)) * ASTR + ks * 8 + (lane & 3);
            af[tm][0] = p[0]; af[tm][1] = p[8 * ASTR]; af[tm][2] = p[4]; af[tm][3] = p[8 * ASTR + 4];
        }
#pragma unroll
        for (int tn = 0; tn < 4; tn++) {
            const unsigned* p = Bb + (ks * 8 + (lane & 3)) * BSTR + wc * 32 + tn * 8 + (lane >> 2);
            bf[tn][0] = p[0]; bf[tn][1] = p[4 * BSTR];
        }
#pragma unroll
        for (int tm = 0; tm < 4; tm++)
#pragma unroll
            for (int tn = 0; tn < 4; tn++) mma8(acc[tm][tn], af[tm], bf[tn]);
    }
}

__global__ void __launch_bounds__(256, 1) k1_edge_rep(
    const float* __restrict__ A, const float* __restrict__ B, const float* __restrict__ bias) {
    extern __shared__ unsigned sm1[];
    unsigned* As = sm1;
    unsigned* Bs = sm1 + 2 * 128 * ASTR;
    const int tid = threadIdx.x, lane = tid & 31, wid = tid >> 5;
    const int wr = wid >> 2, wc = wid & 3;
    const int m0 = blockIdx.x * 128, n0 = blockIdx.y * 128;

    float acc[4][4][4];
#pragma unroll
    for (int a = 0; a < 4; a++)
#pragma unroll
        for (int b = 0; b < 4; b++)
#pragma unroll
            for (int c = 0; c < 4; c++) acc[a][b][c] = 0.f;

    float4 ra[4], rb[4];
#pragma unroll
    for (int i = 0; i < 4; i++) {
        int s = tid + i * 256;
        { int r = s >> 3, kq = s & 7;
          ra[i] = __ldg((const float4*)(A + (size_t)(m0 + r) * HID + kq * 4)); }
        { int kk = s >> 5, cq = s & 31;
          rb[i] = __ldg((const float4*)(B + (size_t)kk * 1024 + n0 + cq * 4)); }
    }
    stA1(As, ra, tid); stB1(Bs, rb, tid);
    __syncthreads();

    int buf = 0;
    for (int kt = 0; kt < 16; kt++) {
        if (kt < 15) {
            int k0 = (kt + 1) * 32;
#pragma unroll
            for (int i = 0; i < 4; i++) {
                int s = tid + i * 256;
                { int r = s >> 3, kq = s & 7;
                  ra[i] = __ldg((const float4*)(A + (size_t)(m0 + r) * HID + k0 + kq * 4)); }
                { int kk = s >> 5, cq = s & 31;
                  rb[i] = __ldg((const float4*)(B + (size_t)(k0 + kk) * 1024 + n0 + cq * 4)); }
            }
        }
        mma_tile1(acc, As + buf * 128 * ASTR, Bs + buf * 32 * BSTR, wr, wc, lane);
        if (kt < 15) { stA1(As + (buf ^ 1) * 128 * ASTR, ra, tid); stB1(Bs + (buf ^ 1) * 32 * BSTR, rb, tid); }
        __syncthreads();
        buf ^= 1;
    }

#pragma unroll
    for (int tm = 0; tm < 4; tm++) {
        int r = m0 + wr * 64 + tm * 16 + (lane >> 2);
#pragma unroll
        for (int tn = 0; tn < 4; tn++) {
            int c = n0 + wc * 32 + tn * 8 + 2 * (lane & 3);
            float2 bb = *(const float2*)(bias + c);
            float2 v0, v1;
            v0.x = __uint_as_float(f2tf(acc[tm][tn][0] + bb.x));
            v0.y = __uint_as_float(f2tf(acc[tm][tn][1] + bb.y));
            v1.x = __uint_as_float(f2tf(acc[tm][tn][2] + bb.x));
            v1.y = __uint_as_float(f2tf(acc[tm][tn][3] + bb.y));
            *(float2*)(g_edge_rep + (size_t)r * 1024 + c) = v0;
            *(float2*)(g_edge_rep + (size_t)(r + 8) * 1024 + c) = v1;
        }
    }
}

// ===========================================================================
// Kernel 2: fused gather -> (prod@Wpc+b)*U -> @Wrel (+prod@Wctx via virtual
// tile) -> +biases+freq. BM=128, BN=256, BK=16, 4-stage cp.async pipeline.
// ===========================================================================
__global__ void __launch_bounds__(256, 1) k2_main(
    const int* __restrict__ pair_idx, const int* __restrict__ obj_preds,
    const float* __restrict__ U,
    const float* __restrict__ bpc,
    const float* __restrict__ Wrel, const float* __restrict__ brel,
    const float* __restrict__ bctx,
    const float* __restrict__ freq, float* __restrict__ out) {
    extern __shared__ char smem[];
    const uint32_t sbu = s2u(smem);
    const float* er = g_edge_rep;

    const int tid = threadIdx.x, lane = tid & 31, wid = tid >> 5;
    const int wr = wid >> 2, wc = wid & 3;
    const int m0 = blockIdx.x * 128;

    int* rows0 = (int*)(smem + OFFI);
    int* rows1 = rows0 + 128;
    int* pp    = rows1 + 128;

    if (tid < 128) {
        int i = m0 + tid;
        int p0 = pair_idx[2 * i], p1 = pair_idx[2 * i + 1];
        rows0[tid] = p0; rows1[tid] = p1;
        pp[tid] = obj_preds[p0] * NOBJC + obj_preds[p1];
    }
    __syncthreads();

    // Cache this thread's A-staging row indices (constant across k-chunks)
    int raT[2][2];  // [half(rows0/rows1)][i]
    int aoff[2], asubk[2];
#pragma unroll
    for (int i = 0; i < 2; i++) {
        int s = tid + i * 256, r = s >> 2, kq = s & 3;
        raT[0][i] = rows0[r];
        raT[1][i] = rows1[r];
        aoff[i] = (r * A2STR + kq * 4) * 4;
        asubk[i] = kq * 4;
    }
    int boff[4], bk[4], bc[4];
#pragma unroll
    for (int i = 0; i < 4; i++) {
        int s = tid + i * 256;
        bk[i] = s >> 6; bc[i] = (s & 63) * 4;
        boff[i] = (bk[i] * B2STR + (s & 63) * 4) * 4;
    }

    // Persistent second-GEMM accumulator: 128x64, warp tile 64x16
    float acc2[4][2][4];
#pragma unroll
    for (int a = 0; a < 4; a++)
#pragma unroll
        for (int b = 0; b < 2; b++)
#pragma unroll
            for (int c = 0; c < 4; c++) acc2[a][b][c] = 0.f;

    for (int nt = 0; nt < 17; nt++) {
        const float* gB = (nt < 16) ? g_wpc : g_wctx;
        const size_t  gstride = (nt < 16) ? 4096 : 256;
        const int     nb = (nt < 16) ? nt * 256 : 0;

        float acc[4][8][4];
#pragma unroll
        for (int a = 0; a < 4; a++)
#pragma unroll
            for (int b = 0; b < 8; b++)
#pragma unroll
                for (int c = 0; c < 4; c++) acc[a][b][c] = 0.f;

        // ---- prologue: stages 0..2 ----
#pragma unroll
        for (int p = 0; p < 3; p++) {
            const int k0 = p * 16;
            const int* ra = raT[0];  // k0 < 512 for p<3
            uint32_t abase = sbu + OFFA + p * ABUF;
            uint32_t bbase = sbu + OFFB + p * BBUF;
#pragma unroll
            for (int i = 0; i < 2; i++)
                cp16(abase + aoff[i], er + (size_t)ra[i] * 1024 + k0 + asubk[i]);
#pragma unroll
            for (int i = 0; i < 4; i++)
                cp16(bbase + boff[i], gB + (size_t)(k0 + bk[i]) * gstride + nb + bc[i]);
            cp_commit();
        }

        // ---- main loop: 64 k-chunks of 16 ----
        for (int kc = 0; kc < 64; kc++) {
            cp_wait2();
            __syncthreads();
            if (kc < 61) {
                const int kn = kc + 3, k0 = kn * 16;
                const int* ra = raT[(k0 >= HID) ? 1 : 0];
                const int st = kn & 3;
                uint32_t abase = sbu + OFFA + st * ABUF;
                uint32_t bbase = sbu + OFFB + st * BBUF;
#pragma unroll
                for (int i = 0; i < 2; i++)
                    cp16(abase + aoff[i], er + (size_t)ra[i] * 1024 + k0 + asubk[i]);
#pragma unroll
                for (int i = 0; i < 4; i++)
                    cp16(bbase + boff[i], gB + (size_t)(k0 + bk[i]) * gstride + nb + bc[i]);
            }
            cp_commit();

            const unsigned* Ab = (const unsigned*)(smem + OFFA + (kc & 3) * ABUF);
            const unsigned* Bb = (const unsigned*)(smem + OFFB + (kc & 3) * BBUF);
#pragma unroll
            for (int ks = 0; ks < 2; ks++) {
                unsigned af[4][4], bf[8][2];
#pragma unroll
                for (int tm = 0; tm < 4; tm++) {
                    const unsigned* p = Ab + (wr * 64 + tm * 16 + (lane >> 2)) * A2STR + ks * 8 + (lane & 3);
                    af[tm][0] = p[0]; af[tm][1] = p[8 * A2STR];
                    af[tm][2] = p[4]; af[tm][3] = p[8 * A2STR + 4];
                }
#pragma unroll
                for (int tn = 0; tn < 8; tn++) {
                    const unsigned* p = Bb + (ks * 8 + (lane & 3)) * B2STR + wc * 64 + tn * 8 + (lane >> 2);
                    bf[tn][0] = p[0]; bf[tn][1] = p[4 * B2STR];
                }
#pragma unroll
                for (int tm = 0; tm < 4; tm++)
#pragma unroll
                    for (int tn = 0; tn < 8; tn++)
                        mma8(acc[tm][tn], af[tm], bf[tn]);
            }
        }
        __syncthreads();

        // ---- epilogue per 128-col half ----
        unsigned* Vs = (unsigned*)(smem + OFFV);
        unsigned* Ws = (unsigned*)(smem + OFFW);
        const int nhmax = (nt < 16) ? 2 : 1;
        for (int nh = 0; nh < nhmax; nh++) {
            // V store (owning warps: wc>>1 == nh)
            if ((wc >> 1) == nh) {
                const int clb = (wc & 1) * 64;
#pragma unroll
                for (int tm = 0; tm < 4; tm++) {
                    int rl = wr * 64 + tm * 16 + (lane >> 2);
                    if (nt < 16) {
                        const float* u0p = U + (size_t)(m0 + rl) * POOL + nt * 256 + nh * 128;
                        const float* u1p = u0p + 8 * POOL;
#pragma unroll
                        for (int tn = 0; tn < 8; tn++) {
                            int vcol = clb + tn * 8 + 2 * (lane & 3);
                            int nG = nt * 256 + nh * 128 + vcol;
                            float2 bb = *(const float2*)(bpc + nG);
                            float2 u0 = __ldg((const float2*)(u0p + vcol));
                            float2 u1 = __ldg((const float2*)(u1p + vcol));
                            Vs[rl * VSTR + vcol]           = f2tf((acc[tm][tn][0] + bb.x) * u0.x);
                            Vs[rl * VSTR + vcol + 1]       = f2tf((acc[tm][tn][1] + bb.y) * u0.y);
                            Vs[(rl + 8) * VSTR + vcol]     = f2tf((acc[tm][tn][2] + bb.x) * u1.x);
                            Vs[(rl + 8) * VSTR + vcol + 1] = f2tf((acc[tm][tn][3] + bb.y) * u1.y);
                        }
                    } else {
#pragma unroll
                        for (int tn = 0; tn < 8; tn++) {
                            int vcol = clb + tn * 8 + 2 * (lane & 3);
                            Vs[rl * VSTR + vcol]           = f2tf(acc[tm][tn][0]);
                            Vs[rl * VSTR + vcol + 1]       = f2tf(acc[tm][tn][1]);
                            Vs[(rl + 8) * VSTR + vcol]     = f2tf(acc[tm][tn][2]);
                            Vs[(rl + 8) * VSTR + vcol + 1] = f2tf(acc[tm][tn][3]);
                        }
                    }
                }
            }
            // Ws store (all threads): [128 k][64 n]
            if (nt < 16) {
                const int n0h = nt * 256 + nh * 128;
#pragma unroll 4
                for (int i = 0; i < 32; i++) {
                    int s = tid + i * 256, k = s >> 6, c = s & 63;
                    float v = (c < NRELC) ? __ldg(Wrel + (size_t)(n0h + k) * NRELC + c) : 0.f;
                    Ws[k * WSTR + c] = f2tf(v);
                }
            } else {
#pragma unroll 4
                for (int i = 0; i < 32; i++) {
                    int s = tid + i * 256, k = s >> 6, c = s & 63;
                    Ws[k * WSTR + c] = (k == c && c < NRELC) ? 0x3F800000u : 0u;
                }
            }
            __syncthreads();

            // acc2 += V(128x128) @ Ws(128x64)
#pragma unroll
            for (int kk = 0; kk < 16; kk++) {
                unsigned af[4][4], bf[2][2];
#pragma unroll
                for (int tm = 0; tm < 4; tm++) {
                    const unsigned* p = Vs + (wr * 64 + tm * 16 + (lane >> 2)) * VSTR + kk * 8 + (lane & 3);
                    af[tm][0] = p[0]; af[tm][1] = p[8 * VSTR];
                    af[tm][2] = p[4]; af[tm][3] = p[8 * VSTR + 4];
                }
#pragma unroll
                for (int tn = 0; tn < 2; tn++) {
                    const unsigned* p = Ws + (kk * 8 + (lane & 3)) * WSTR + wc * 16 + tn * 8 + (lane >> 2);
                    bf[tn][0] = p[0]; bf[tn][1] = p[4 * WSTR];
                }
#pragma unroll
                for (int tm = 0; tm < 4; tm++)
#pragma unroll
                    for (int tn = 0; tn < 2; tn++)
                        mma8(acc2[tm][tn], af[tm], bf[tn]);
            }
            __syncthreads();
        }
    }

    // ---- final epilogue: + b_rel + b_ctx + freq_table[pair_pred] ----
#pragma unroll
    for (int tm = 0; tm < 4; tm++) {
        int rl = wr * 64 + tm * 16 + (lane >> 2);
#pragma unroll
        for (int tn = 0; tn < 2; tn++) {
            int c = wc * 16 + tn * 8 + 2 * (lane & 3);
#pragma unroll
            for (int q = 0; q < 4; q++) {
                int row = rl + ((q >= 2) ? 8 : 0);
                int col = c + (q & 1);
                if (col < NRELC) {
                    float v = acc2[tm][tn][q] + __ldg(brel + col) + __ldg(bctx + col)
                            + __ldg(freq + (size_t)pp[row] * NRELC + col);
                    out[(size_t)(m0 + row) * NRELC + col] = v;
                }
            }
        }
    }
}

// ===========================================================================
// Launch
// ===========================================================================
extern "C" void kernel_launch(void* const* d_in, const int* in_sizes, int n_in,
                              void* d_out, int out_size) {
    (void)in_sizes; (void)n_in; (void)out_size;
    const float* edge_ctx  = (const float*)d_in[0];
    const int*   obj_preds = (const int*)d_in[1];
    const int*   pair_idx  = (const int*)d_in[2];
    const float* U         = (const float*)d_in[3];
    const float* Wpe       = (const float*)d_in[4];
    const float* bpe       = (const float*)d_in[5];
    const float* Wpc       = (const float*)d_in[6];
    const float* bpc       = (const float*)d_in[7];
    const float* Wrel      = (const float*)d_in[8];
    const float* brel      = (const float*)d_in[9];
    const float* Wctx      = (const float*)d_in[10];
    const float* bctx      = (const float*)d_in[11];
    const float* freq      = (const float*)d_in[12];
    float* out = (float*)d_out;

    cudaFuncSetAttribute(k1_edge_rep, cudaFuncAttributeMaxDynamicSharedMemorySize, K1_SMEM);
    cudaFuncSetAttribute(k2_main,     cudaFuncAttributeMaxDynamicSharedMemorySize, K2S);

    k0_prep<<<4096 + 1024, 256>>>(Wpc, Wctx);
    k1_edge_rep<<<dim3(64, 8), 256, K1_SMEM>>>(edge_ctx, Wpe, bpe);
    k2_main<<<512, 256, K2S>>>(pair_idx, obj_preds, U, bpc,
                               Wrel, brel, bctx, freq, out);
}